// round 1
// baseline (speedup 1.0000x reference)
#include <cuda_runtime.h>

#define D_DIM 512
#define L_SEQ 8192
#define BATCH 8
#define VOCAB 256
#define KW 5
#define T_TILE 24
#define TPR 342            // ceil(8192 / 24)
#define OUTL 4096

// Scratch (allocation-free rule: __device__ globals)
__device__ float g_Wt[KW * D_DIM * D_DIM];    // [k][i][d]   transposed conv_w
__device__ float g_P[VOCAB * KW * D_DIM];     // [v][k][d]   token->conv-contribution table

// ---------------------------------------------------------------------------
// Kernel A: transpose conv_w [d][i][k] -> Wt [k][i][d] for coalesced GEMM reads
// ---------------------------------------------------------------------------
__global__ void transpose_w_kernel(const float* __restrict__ conv_w) {
    int g = blockIdx.x * blockDim.x + threadIdx.x;   // 0 .. 512*512-1
    int d = g & (D_DIM - 1);
    int i = g >> 9;
    #pragma unroll
    for (int k = 0; k < KW; k++) {
        g_Wt[k * D_DIM * D_DIM + i * D_DIM + d] = conv_w[(d * D_DIM + i) * KW + k];
    }
}

// ---------------------------------------------------------------------------
// Kernel B: P[v][k][d] = sum_i emb[v][i] * Wt[k][i][d]
// Tiled fp32 GEMM: 64v x 64d tile per block, 256 threads, 4x4 per thread.
// grid = (8 d-tiles, 4 v-tiles, 5 k)
// ---------------------------------------------------------------------------
__global__ __launch_bounds__(256) void p_gemm_kernel(const float* __restrict__ emb) {
    const int k  = blockIdx.z;
    const int v0 = blockIdx.y * 64;
    const int d0 = blockIdx.x * 64;
    const int tid = threadIdx.x;
    const int tx = tid & 15;        // d quad
    const int ty = tid >> 4;        // v quad

    __shared__ float As[16][64];    // [ii][vv]  emb tile
    __shared__ float Bs[16][64];    // [ii][dd]  Wt tile

    const float* Wt = g_Wt + (size_t)k * D_DIM * D_DIM;

    float c[4][4];
    #pragma unroll
    for (int r = 0; r < 4; r++)
        #pragma unroll
        for (int q = 0; q < 4; q++) c[r][q] = 0.f;

    for (int i0 = 0; i0 < D_DIM; i0 += 16) {
        // Load A tile: thread t loads float4 along i for one v row.
        {
            int vv = tid & 63;
            int iib = (tid >> 6) * 4;
            float4 a = *(const float4*)&emb[(size_t)(v0 + vv) * D_DIM + i0 + iib];
            As[iib + 0][vv] = a.x;
            As[iib + 1][vv] = a.y;
            As[iib + 2][vv] = a.z;
            As[iib + 3][vv] = a.w;
        }
        // Load B tile: coalesced float4 along d.
        {
            int ii = tid >> 4;
            int dd = (tid & 15) * 4;
            *(float4*)&Bs[ii][dd] = *(const float4*)&Wt[(size_t)(i0 + ii) * D_DIM + d0 + dd];
        }
        __syncthreads();
        #pragma unroll
        for (int ii = 0; ii < 16; ii++) {
            float4 a = *(const float4*)&As[ii][ty * 4];
            float4 b = *(const float4*)&Bs[ii][tx * 4];
            c[0][0] += a.x * b.x; c[0][1] += a.x * b.y; c[0][2] += a.x * b.z; c[0][3] += a.x * b.w;
            c[1][0] += a.y * b.x; c[1][1] += a.y * b.y; c[1][2] += a.y * b.z; c[1][3] += a.y * b.w;
            c[2][0] += a.z * b.x; c[2][1] += a.z * b.y; c[2][2] += a.z * b.z; c[2][3] += a.z * b.w;
            c[3][0] += a.w * b.x; c[3][1] += a.w * b.y; c[3][2] += a.w * b.z; c[3][3] += a.w * b.w;
        }
        __syncthreads();
    }

    #pragma unroll
    for (int r = 0; r < 4; r++) {
        float4 o = make_float4(c[r][0], c[r][1], c[r][2], c[r][3]);
        *(float4*)&g_P[((size_t)(v0 + ty * 4 + r) * KW + k) * D_DIM + d0 + tx * 4] = o;
    }
}

// ---------------------------------------------------------------------------
// Kernel C: fully fused GBST main pass.
// One CTA = 24 consecutive positions of one row (aligned to 12, so all
// b=2/3/4 pooling blocks and DS=2 pairs are tile-local). 256 threads,
// thread t owns channels {2t, 2t+1} (float2).
// ---------------------------------------------------------------------------
__global__ __launch_bounds__(256, 2) void gbst_main_kernel(
    const int* __restrict__ ids,
    const float* __restrict__ conv_b,
    const float* __restrict__ score_w,
    float* __restrict__ out)
{
    __shared__ int   sid[T_TILE + 4];
    __shared__ float red[T_TILE][8];
    __shared__ float t_s[T_TILE];
    __shared__ float wsm[T_TILE][4];

    const int row  = blockIdx.x / TPR;
    const int tile = blockIdx.x - row * TPR;
    const int r0   = tile * T_TILE;
    const int Tcur = (L_SEQ - r0 < T_TILE) ? (L_SEQ - r0) : T_TILE;  // 24 or 8
    const int tid  = threadIdx.x;
    const int lane = tid & 31;
    const int warp = tid >> 5;

    if (tid < T_TILE + 4) {
        int j = r0 + tid - 2;
        sid[tid] = (j >= 0 && j < L_SEQ) ? ids[row * L_SEQ + j] : 0;  // id 0 -> P row 0 == zeros
    }
    __syncthreads();

    const float2 cb = ((const float2*)conv_b)[tid];
    const float2 sw = ((const float2*)score_w)[tid];

    // Phase 1: conv output via table gather, + scalar score partials
    float2 xs[T_TILE];
    float  p[T_TILE];
    #pragma unroll
    for (int l = 0; l < T_TILE; l++) {
        float ax = 0.f, ay = 0.f;
        if (l < Tcur) {
            ax = cb.x; ay = cb.y;
            #pragma unroll
            for (int k = 0; k < KW; k++) {
                int v = sid[l + k];
                float2 pv = ((const float2*)g_P)[(v * KW + k) * (D_DIM / 2) + tid];
                ax += pv.x; ay += pv.y;
            }
        }
        xs[l] = make_float2(ax, ay);
        p[l]  = ax * sw.x + ay * sw.y;
    }

    // Phase 2: block-reduce t[l] = x[l] . score_w
    #pragma unroll
    for (int l = 0; l < T_TILE; l++) {
        float v = p[l];
        v += __shfl_xor_sync(0xffffffffu, v, 16);
        v += __shfl_xor_sync(0xffffffffu, v, 8);
        v += __shfl_xor_sync(0xffffffffu, v, 4);
        v += __shfl_xor_sync(0xffffffffu, v, 2);
        v += __shfl_xor_sync(0xffffffffu, v, 1);
        if (lane == 0) red[l][warp] = v;
    }
    __syncthreads();
    if (tid < T_TILE) {
        float s = 0.f;
        #pragma unroll
        for (int w = 0; w < 8; w++) s += red[tid][w];
        t_s[tid] = s;          // == 0 for padded tail (xs were zeroed)
    }
    __syncthreads();

    // Phase 3: per-position block-mean scores + softmax weights (one thread/pos)
    if (tid < T_TILE) {
        const int l = tid;
        float s1 = t_s[l];
        int j2 = l & ~1;
        float s2 = (t_s[j2] + t_s[j2 + 1]) * 0.5f;
        int j3 = l - (l % 3);
        float s3 = (t_s[j3] + t_s[j3 + 1] + t_s[j3 + 2]) * (1.f / 3.f);
        int j4 = l & ~3;
        float s4 = (t_s[j4] + t_s[j4 + 1] + t_s[j4 + 2] + t_s[j4 + 3]) * 0.25f;
        float mx = fmaxf(fmaxf(s1, s2), fmaxf(s3, s4));
        float e1 = expf(s1 - mx);
        float e2 = expf(s2 - mx);
        float e3 = expf(s3 - mx);
        float e4 = expf(s4 - mx);
        float inv = 1.f / (e1 + e2 + e3 + e4);
        wsm[l][0] = e1 * inv;
        wsm[l][1] = e2 * inv;
        wsm[l][2] = e3 * inv;
        wsm[l][3] = e4 * inv;
    }
    __syncthreads();

    // Phase 4: pooled candidates (registers), weighted combine, DS=2 pool, store
    float2 p3[T_TILE / 3];
    #pragma unroll
    for (int j = 0; j < T_TILE / 3; j++) {
        p3[j].x = (xs[3 * j].x + xs[3 * j + 1].x + xs[3 * j + 2].x) * (1.f / 3.f);
        p3[j].y = (xs[3 * j].y + xs[3 * j + 1].y + xs[3 * j + 2].y) * (1.f / 3.f);
    }
    float2 p4[T_TILE / 4];
    #pragma unroll
    for (int j = 0; j < T_TILE / 4; j++) {
        p4[j].x = (xs[4 * j].x + xs[4 * j + 1].x + xs[4 * j + 2].x + xs[4 * j + 3].x) * 0.25f;
        p4[j].y = (xs[4 * j].y + xs[4 * j + 1].y + xs[4 * j + 2].y + xs[4 * j + 3].y) * 0.25f;
    }

    #pragma unroll
    for (int j = 0; j < T_TILE / 2; j++) {
        const int l0 = 2 * j, l1 = 2 * j + 1;
        if (l0 < Tcur) {
            float w10 = wsm[l0][0], w11 = wsm[l1][0];
            float w2  = wsm[l0][1] + wsm[l1][1];
            float w30 = wsm[l0][2], w31 = wsm[l1][2];
            float w4  = wsm[l0][3] + wsm[l1][3];
            float2 a = xs[l0], b = xs[l1];
            float m2x = (a.x + b.x) * 0.5f;
            float m2y = (a.y + b.y) * 0.5f;
            float ox = w10 * a.x + w11 * b.x + w2 * m2x
                     + w30 * p3[l0 / 3].x + w31 * p3[l1 / 3].x
                     + w4 * p4[j >> 1].x;
            float oy = w10 * a.y + w11 * b.y + w2 * m2y
                     + w30 * p3[l0 / 3].y + w31 * p3[l1 / 3].y
                     + w4 * p4[j >> 1].y;
            float2 o = make_float2(ox * 0.5f, oy * 0.5f);
            ((float2*)out)[((size_t)row * OUTL + (r0 >> 1) + j) * (D_DIM / 2) + tid] = o;
        }
    }
}

// ---------------------------------------------------------------------------
extern "C" void kernel_launch(void* const* d_in, const int* in_sizes, int n_in,
                              void* d_out, int out_size) {
    const int*   ids     = (const int*)d_in[0];
    const float* emb     = (const float*)d_in[1];
    const float* conv_w  = (const float*)d_in[2];
    const float* conv_b  = (const float*)d_in[3];
    const float* score_w = (const float*)d_in[4];
    float* out = (float*)d_out;

    transpose_w_kernel<<<(D_DIM * D_DIM) / 256, 256>>>(conv_w);

    dim3 gg(D_DIM / 64, VOCAB / 64, KW);
    p_gemm_kernel<<<gg, 256>>>(emb);

    gbst_main_kernel<<<BATCH * TPR, 256>>>(ids, conv_b, score_w, out);
}

// round 2
// speedup vs baseline: 1.2275x; 1.2275x over previous
#include <cuda_runtime.h>
#include <cuda_fp16.h>

#define D_DIM 512
#define L_SEQ 8192
#define BATCH 8
#define VOCAB 256
#define KW 5
#define T_TILE 24
#define TPR 342            // ceil(8192 / 24)
#define OUTL 4096

// Scratch (allocation-free rule: __device__ globals)
__device__ float  g_Wt[KW * D_DIM * D_DIM];    // [k][i][d]   transposed conv_w
__device__ __half g_Ph[VOCAB * KW * D_DIM];    // [v][k][d]   fp16 conv-contribution table
__device__ float  g_u[D_DIM * KW];             // [i][k]  u[k,i] = sum_d conv_w[d,i,k]*sw[d]
__device__ float  g_sT[VOCAB * KW];            // [v][k]  exact scalar score table
__device__ float  g_bs[1];                     // conv_b . score_w

// ---------------------------------------------------------------------------
// PREP: blocks 0..255  : coalesced smem-tiled transpose conv_w[d][i][k] -> Wt[k][i][d]
//       blocks 256..295: u[k][i] = sum_d conv_w[d][i][k] * score_w[d]
// ---------------------------------------------------------------------------
__global__ __launch_bounds__(256) void prep_kernel(const float* __restrict__ cw,
                                                   const float* __restrict__ sw) {
    __shared__ __align__(16) float s[32][165];   // padded: stride 165 -> conflict-free
    const int tid = threadIdx.x;

    if (blockIdx.x < 256) {
        const int d0 = (blockIdx.x & 15) * 32;
        const int i0 = (blockIdx.x >> 4) * 32;
        // Load 32 d-rows x 160 floats (i0..i0+31, all k), coalesced per row.
        #pragma unroll
        for (int j = 0; j < 20; j++) {
            int idx = tid + 256 * j;            // 0..5119
            int dr  = idx / 160;
            int pos = idx - dr * 160;
            s[dr][pos] = cw[(size_t)(d0 + dr) * (D_DIM * KW) + i0 * KW + pos];
        }
        __syncthreads();
        // Store coalesced along d.
        #pragma unroll
        for (int j = 0; j < 20; j++) {
            int w   = tid + 256 * j;
            int k   = w >> 10;
            int rem = w & 1023;
            int il  = rem >> 5;
            int dl  = rem & 31;
            g_Wt[(size_t)k * (D_DIM * D_DIM) + (size_t)(i0 + il) * D_DIM + d0 + dl] =
                s[dl][il * 5 + k];
        }
    } else {
        // u block: 64 flattened (i,k) pairs per block, d split 4 ways.
        const int ub    = blockIdx.x - 256;     // 0..39
        const int c     = ub * 64 + (tid & 63); // flat i*5+k
        const int chunk = tid >> 6;             // 0..3
        float part = 0.f;
        for (int d = chunk * 128; d < chunk * 128 + 128; d++)
            part += cw[(size_t)d * (D_DIM * KW) + c] * sw[d];
        float* sf = (float*)s;
        sf[chunk * 64 + (tid & 63)] = part;
        __syncthreads();
        if (tid < 64)
            g_u[ub * 64 + tid] = sf[tid] + sf[64 + tid] + sf[128 + tid] + sf[192 + tid];
    }
}

// ---------------------------------------------------------------------------
// BUILD: blocks 0..159  : P GEMM  (64v x 64d tile, fp32 acc, fp16 store)
//        blocks 160..415: sT[v][k] = emb[v] . u[k]   (exact fp32)
//        block 416      : g_bs = conv_b . score_w
// ---------------------------------------------------------------------------
__global__ __launch_bounds__(256) void build_kernel(const float* __restrict__ emb,
                                                    const float* __restrict__ cb,
                                                    const float* __restrict__ sw) {
    __shared__ __align__(16) float sm[2 * 16 * 64];   // 8 KB
    const int tid = threadIdx.x;
    const int b = blockIdx.x;

    if (b < 160) {
        const int k   = b / 32;
        const int rem = b - k * 32;
        const int v0  = (rem >> 3) * 64;
        const int d0  = (rem & 7) * 64;
        const int tx = tid & 15;
        const int ty = tid >> 4;
        float (*As)[64] = (float(*)[64])sm;
        float (*Bs)[64] = (float(*)[64])(sm + 16 * 64);
        const float* Wt = g_Wt + (size_t)k * D_DIM * D_DIM;

        float c[4][4];
        #pragma unroll
        for (int r = 0; r < 4; r++)
            #pragma unroll
            for (int q = 0; q < 4; q++) c[r][q] = 0.f;

        for (int i0 = 0; i0 < D_DIM; i0 += 16) {
            {
                int vv  = tid & 63;
                int iib = (tid >> 6) * 4;
                float4 a = *(const float4*)&emb[(size_t)(v0 + vv) * D_DIM + i0 + iib];
                As[iib + 0][vv] = a.x;
                As[iib + 1][vv] = a.y;
                As[iib + 2][vv] = a.z;
                As[iib + 3][vv] = a.w;
            }
            {
                int ii = tid >> 4;
                int dd = (tid & 15) * 4;
                *(float4*)&Bs[ii][dd] = *(const float4*)&Wt[(size_t)(i0 + ii) * D_DIM + d0 + dd];
            }
            __syncthreads();
            #pragma unroll
            for (int ii = 0; ii < 16; ii++) {
                float4 a = *(const float4*)&As[ii][ty * 4];
                float4 bb = *(const float4*)&Bs[ii][tx * 4];
                c[0][0] += a.x * bb.x; c[0][1] += a.x * bb.y; c[0][2] += a.x * bb.z; c[0][3] += a.x * bb.w;
                c[1][0] += a.y * bb.x; c[1][1] += a.y * bb.y; c[1][2] += a.y * bb.z; c[1][3] += a.y * bb.w;
                c[2][0] += a.z * bb.x; c[2][1] += a.z * bb.y; c[2][2] += a.z * bb.z; c[2][3] += a.z * bb.w;
                c[3][0] += a.w * bb.x; c[3][1] += a.w * bb.y; c[3][2] += a.w * bb.z; c[3][3] += a.w * bb.w;
            }
            __syncthreads();
        }

        #pragma unroll
        for (int r = 0; r < 4; r++) {
            __half2 h0 = __floats2half2_rn(c[r][0], c[r][1]);
            __half2 h1 = __floats2half2_rn(c[r][2], c[r][3]);
            size_t base = ((size_t)(v0 + ty * 4 + r) * KW + k) * D_DIM + d0 + tx * 4;
            __half2* dst = (__half2*)(g_Ph + base);
            dst[0] = h0;
            dst[1] = h1;
        }
    } else if (b < 416) {
        const int v = b - 160;
        float part[5] = {0.f, 0.f, 0.f, 0.f, 0.f};
        #pragma unroll
        for (int j = 0; j < 2; j++) {
            int i = tid + 256 * j;
            float e = emb[(size_t)v * D_DIM + i];
            #pragma unroll
            for (int k = 0; k < 5; k++) part[k] += e * g_u[i * 5 + k];
        }
        #pragma unroll
        for (int k = 0; k < 5; k++) {
            float x = part[k];
            x += __shfl_xor_sync(0xffffffffu, x, 16);
            x += __shfl_xor_sync(0xffffffffu, x, 8);
            x += __shfl_xor_sync(0xffffffffu, x, 4);
            x += __shfl_xor_sync(0xffffffffu, x, 2);
            x += __shfl_xor_sync(0xffffffffu, x, 1);
            if ((tid & 31) == 0) sm[(tid >> 5) * 5 + k] = x;
        }
        __syncthreads();
        if (tid < 5) {
            float ssum = 0.f;
            #pragma unroll
            for (int w = 0; w < 8; w++) ssum += sm[w * 5 + tid];
            g_sT[v * 5 + tid] = ssum;
        }
    } else {
        float part = cb[tid] * sw[tid] + cb[tid + 256] * sw[tid + 256];
        part += __shfl_xor_sync(0xffffffffu, part, 16);
        part += __shfl_xor_sync(0xffffffffu, part, 8);
        part += __shfl_xor_sync(0xffffffffu, part, 4);
        part += __shfl_xor_sync(0xffffffffu, part, 2);
        part += __shfl_xor_sync(0xffffffffu, part, 1);
        if ((tid & 31) == 0) sm[tid >> 5] = part;
        __syncthreads();
        if (tid == 0) {
            float ssum = 0.f;
            #pragma unroll
            for (int w = 0; w < 8; w++) ssum += sm[w];
            g_bs[0] = ssum;
        }
    }
}

// ---------------------------------------------------------------------------
// MAIN: fused GBST. One CTA = 24 positions of one row. 256 threads,
// thread t owns channels {2t, 2t+1}. Candidates from fp16 P (fp32 acc),
// scores from exact fp32 scalar table.
// ---------------------------------------------------------------------------
__global__ __launch_bounds__(256, 2) void gbst_main_kernel(
    const int* __restrict__ ids,
    const float* __restrict__ conv_b,
    float* __restrict__ out)
{
    __shared__ int   sid[T_TILE + 4];
    __shared__ float t_s[T_TILE];
    __shared__ float wsm[T_TILE][4];

    const int row  = blockIdx.x / TPR;
    const int tile = blockIdx.x - row * TPR;
    const int r0   = tile * T_TILE;
    const int Tcur = (L_SEQ - r0 < T_TILE) ? (L_SEQ - r0) : T_TILE;  // 24 or 8
    const int tid  = threadIdx.x;

    if (tid < T_TILE + 4) {
        int j = r0 + tid - 2;
        sid[tid] = (j >= 0 && j < L_SEQ) ? ids[row * L_SEQ + j] : 0;  // id 0 -> zero row
    }
    __syncthreads();

    const float2 cb = ((const float2*)conv_b)[tid];
    const __half2* __restrict__ Pb = (const __half2*)g_Ph;  // [(v*5+k)*256 + tid]

    // Phase 1: conv output via fp16 table gather (fp32 accumulate)
    float2 xs[T_TILE];
    #pragma unroll
    for (int l = 0; l < T_TILE; l++) {
        float ax = 0.f, ay = 0.f;
        if (l < Tcur) {
            ax = cb.x; ay = cb.y;
            #pragma unroll
            for (int k = 0; k < KW; k++) {
                int v = sid[l + k];
                float2 f = __half22float2(Pb[(v * KW + k) * (D_DIM / 2) + tid]);
                ax += f.x; ay += f.y;
            }
        }
        xs[l] = make_float2(ax, ay);
    }

    // Phase 2: exact scalar scores from table
    if (tid < T_TILE) {
        float s = 0.f;
        if (tid < Tcur) {
            s = g_bs[0];
            #pragma unroll
            for (int k = 0; k < KW; k++) s += g_sT[sid[tid + k] * KW + k];
        }
        t_s[tid] = s;
    }
    __syncthreads();

    // Phase 3: per-position block-mean scores + softmax weights
    if (tid < T_TILE) {
        const int l = tid;
        float s1 = t_s[l];
        int j2 = l & ~1;
        float s2 = (t_s[j2] + t_s[j2 + 1]) * 0.5f;
        int j3 = l - (l % 3);
        float s3 = (t_s[j3] + t_s[j3 + 1] + t_s[j3 + 2]) * (1.f / 3.f);
        int j4 = l & ~3;
        float s4 = (t_s[j4] + t_s[j4 + 1] + t_s[j4 + 2] + t_s[j4 + 3]) * 0.25f;
        float mx = fmaxf(fmaxf(s1, s2), fmaxf(s3, s4));
        float e1 = expf(s1 - mx);
        float e2 = expf(s2 - mx);
        float e3 = expf(s3 - mx);
        float e4 = expf(s4 - mx);
        float inv = 1.f / (e1 + e2 + e3 + e4);
        wsm[l][0] = e1 * inv;
        wsm[l][1] = e2 * inv;
        wsm[l][2] = e3 * inv;
        wsm[l][3] = e4 * inv;
    }
    __syncthreads();

    // Phase 4: pooled candidates, weighted combine, DS=2 pool, store
    float2 p3[T_TILE / 3];
    #pragma unroll
    for (int j = 0; j < T_TILE / 3; j++) {
        p3[j].x = (xs[3 * j].x + xs[3 * j + 1].x + xs[3 * j + 2].x) * (1.f / 3.f);
        p3[j].y = (xs[3 * j].y + xs[3 * j + 1].y + xs[3 * j + 2].y) * (1.f / 3.f);
    }
    float2 p4[T_TILE / 4];
    #pragma unroll
    for (int j = 0; j < T_TILE / 4; j++) {
        p4[j].x = (xs[4 * j].x + xs[4 * j + 1].x + xs[4 * j + 2].x + xs[4 * j + 3].x) * 0.25f;
        p4[j].y = (xs[4 * j].y + xs[4 * j + 1].y + xs[4 * j + 2].y + xs[4 * j + 3].y) * 0.25f;
    }

    #pragma unroll
    for (int j = 0; j < T_TILE / 2; j++) {
        const int l0 = 2 * j, l1 = 2 * j + 1;
        if (l0 < Tcur) {
            float w10 = wsm[l0][0], w11 = wsm[l1][0];
            float w2  = wsm[l0][1] + wsm[l1][1];
            float w30 = wsm[l0][2], w31 = wsm[l1][2];
            float w4  = wsm[l0][3] + wsm[l1][3];
            float2 a = xs[l0], bb = xs[l1];
            float m2x = (a.x + bb.x) * 0.5f;
            float m2y = (a.y + bb.y) * 0.5f;
            float ox = w10 * a.x + w11 * bb.x + w2 * m2x
                     + w30 * p3[l0 / 3].x + w31 * p3[l1 / 3].x
                     + w4 * p4[j >> 1].x;
            float oy = w10 * a.y + w11 * bb.y + w2 * m2y
                     + w30 * p3[l0 / 3].y + w31 * p3[l1 / 3].y
                     + w4 * p4[j >> 1].y;
            float2 o = make_float2(ox * 0.5f, oy * 0.5f);
            ((float2*)out)[((size_t)row * OUTL + (r0 >> 1) + j) * (D_DIM / 2) + tid] = o;
        }
    }
}

// ---------------------------------------------------------------------------
extern "C" void kernel_launch(void* const* d_in, const int* in_sizes, int n_in,
                              void* d_out, int out_size) {
    const int*   ids     = (const int*)d_in[0];
    const float* emb     = (const float*)d_in[1];
    const float* conv_w  = (const float*)d_in[2];
    const float* conv_b  = (const float*)d_in[3];
    const float* score_w = (const float*)d_in[4];
    float* out = (float*)d_out;

    prep_kernel<<<296, 256>>>(conv_w, score_w);
    build_kernel<<<417, 256>>>(emb, conv_b, score_w);
    gbst_main_kernel<<<BATCH * TPR, 256>>>(ids, conv_b, out);
}

// round 4
// speedup vs baseline: 1.4880x; 1.2123x over previous
#include <cuda_runtime.h>
#include <cuda_fp16.h>

#define D_DIM 512
#define L_SEQ 8192
#define BATCH 8
#define VOCAB 256
#define KW 5
#define T_TILE 12
#define TPR 683            // ceil(8192 / 12)
#define OUTL 4096

// Scratch (allocation-free rule: __device__ globals)
__device__ float  g_Wt[KW * D_DIM * D_DIM];                 // [k][i][d]
__device__ __align__(16) __half g_Ph[VOCAB * KW * D_DIM];   // [v][k][d] fp16 table
__device__ float  g_u[D_DIM * KW];                          // [i][k]
__device__ float  g_sT[VOCAB * KW];                         // [v][k] exact score table
__device__ float  g_bs[1];                                  // conv_b . score_w

// ---------------------------------------------------------------------------
// PREP: blocks 0..511  : transpose conv_w[d][i][k] -> Wt[k][i][d], 32d x 16i x 5k tiles
//       blocks 512..551: u[i*5+k] = sum_d conv_w[d][i][k] * score_w[d]
// ---------------------------------------------------------------------------
__global__ __launch_bounds__(256) void prep_kernel(const float* __restrict__ cw,
                                                   const float* __restrict__ sw) {
    __shared__ __align__(16) float s[32][85];   // 10.9 KB, stride 85 -> conflict-free
    const int tid = threadIdx.x;

    if (blockIdx.x < 512) {
        const int d0 = (blockIdx.x & 15) * 32;
        const int i0 = (blockIdx.x >> 4) * 16;
        // Load 32 d-rows x 80 floats (16 i, 5 k), coalesced runs of 80.
        #pragma unroll
        for (int j = 0; j < 10; j++) {
            int idx = tid + 256 * j;            // 0..2559
            int dr  = idx / 80;
            int pos = idx - dr * 80;
            s[dr][pos] = cw[(size_t)(d0 + dr) * (D_DIM * KW) + i0 * KW + pos];
        }
        __syncthreads();
        // Store coalesced along d.
        #pragma unroll
        for (int j = 0; j < 10; j++) {
            int w  = tid + 256 * j;
            int dl = w & 31;
            int il = (w >> 5) & 15;
            int k  = w >> 9;
            g_Wt[(size_t)k * (D_DIM * D_DIM) + (size_t)(i0 + il) * D_DIM + d0 + dl] =
                s[dl][il * 5 + k];
        }
    } else {
        const int ub    = blockIdx.x - 512;     // 0..39
        const int c     = ub * 64 + (tid & 63); // flat i*5+k
        const int chunk = tid >> 6;             // 0..3
        float part = 0.f;
        for (int d = chunk * 128; d < chunk * 128 + 128; d++)
            part += cw[(size_t)d * (D_DIM * KW) + c] * sw[d];
        float* sf = (float*)s;
        sf[chunk * 64 + (tid & 63)] = part;
        __syncthreads();
        if (tid < 64)
            g_u[ub * 64 + tid] = sf[tid] + sf[64 + tid] + sf[128 + tid] + sf[192 + tid];
    }
}

// ---------------------------------------------------------------------------
// BUILD: blocks 0..159  : P GEMM  (64v x 64d tile, fp32 acc, fp16 store)
//        blocks 160..415: sT[v][k] = emb[v] . u[k]  (exact fp32)
//        block 416      : g_bs = conv_b . score_w
// ---------------------------------------------------------------------------
__global__ __launch_bounds__(256) void build_kernel(const float* __restrict__ emb,
                                                    const float* __restrict__ cb,
                                                    const float* __restrict__ sw) {
    __shared__ __align__(16) float sm[2 * 16 * 64];   // 8 KB
    const int tid = threadIdx.x;
    const int b = blockIdx.x;

    if (b < 160) {
        const int k   = b / 32;
        const int rem = b - k * 32;
        const int v0  = (rem >> 3) * 64;
        const int d0  = (rem & 7) * 64;
        const int tx = tid & 15;
        const int ty = tid >> 4;
        float (*As)[64] = (float(*)[64])sm;
        float (*Bs)[64] = (float(*)[64])(sm + 16 * 64);
        const float* Wt = g_Wt + (size_t)k * D_DIM * D_DIM;

        float c[4][4];
        #pragma unroll
        for (int r = 0; r < 4; r++)
            #pragma unroll
            for (int q = 0; q < 4; q++) c[r][q] = 0.f;

        for (int i0 = 0; i0 < D_DIM; i0 += 16) {
            {
                int vv  = tid & 63;
                int iib = (tid >> 6) * 4;
                float4 a = *(const float4*)&emb[(size_t)(v0 + vv) * D_DIM + i0 + iib];
                As[iib + 0][vv] = a.x;
                As[iib + 1][vv] = a.y;
                As[iib + 2][vv] = a.z;
                As[iib + 3][vv] = a.w;
            }
            {
                int ii = tid >> 4;
                int dd = (tid & 15) * 4;
                *(float4*)&Bs[ii][dd] = *(const float4*)&Wt[(size_t)(i0 + ii) * D_DIM + d0 + dd];
            }
            __syncthreads();
            #pragma unroll
            for (int ii = 0; ii < 16; ii++) {
                float4 a = *(const float4*)&As[ii][ty * 4];
                float4 bb = *(const float4*)&Bs[ii][tx * 4];
                c[0][0] += a.x * bb.x; c[0][1] += a.x * bb.y; c[0][2] += a.x * bb.z; c[0][3] += a.x * bb.w;
                c[1][0] += a.y * bb.x; c[1][1] += a.y * bb.y; c[1][2] += a.y * bb.z; c[1][3] += a.y * bb.w;
                c[2][0] += a.z * bb.x; c[2][1] += a.z * bb.y; c[2][2] += a.z * bb.z; c[2][3] += a.z * bb.w;
                c[3][0] += a.w * bb.x; c[3][1] += a.w * bb.y; c[3][2] += a.w * bb.z; c[3][3] += a.w * bb.w;
            }
            __syncthreads();
        }

        #pragma unroll
        for (int r = 0; r < 4; r++) {
            __half2 h0 = __floats2half2_rn(c[r][0], c[r][1]);
            __half2 h1 = __floats2half2_rn(c[r][2], c[r][3]);
            size_t base = ((size_t)(v0 + ty * 4 + r) * KW + k) * D_DIM + d0 + tx * 4;
            __half2* dst = (__half2*)(g_Ph + base);
            dst[0] = h0;
            dst[1] = h1;
        }
    } else if (b < 416) {
        const int v = b - 160;
        float part[5] = {0.f, 0.f, 0.f, 0.f, 0.f};
        #pragma unroll
        for (int j = 0; j < 2; j++) {
            int i = tid + 256 * j;
            float e = emb[(size_t)v * D_DIM + i];
            #pragma unroll
            for (int k = 0; k < 5; k++) part[k] += e * g_u[i * 5 + k];
        }
        #pragma unroll
        for (int k = 0; k < 5; k++) {
            float x = part[k];
            x += __shfl_xor_sync(0xffffffffu, x, 16);
            x += __shfl_xor_sync(0xffffffffu, x, 8);
            x += __shfl_xor_sync(0xffffffffu, x, 4);
            x += __shfl_xor_sync(0xffffffffu, x, 2);
            x += __shfl_xor_sync(0xffffffffu, x, 1);
            if ((tid & 31) == 0) sm[(tid >> 5) * 5 + k] = x;
        }
        __syncthreads();
        if (tid < 5) {
            float ssum = 0.f;
            #pragma unroll
            for (int w = 0; w < 8; w++) ssum += sm[w * 5 + tid];
            g_sT[v * 5 + tid] = ssum;
        }
    } else {
        float part = cb[tid] * sw[tid] + cb[tid + 256] * sw[tid + 256];
        part += __shfl_xor_sync(0xffffffffu, part, 16);
        part += __shfl_xor_sync(0xffffffffu, part, 8);
        part += __shfl_xor_sync(0xffffffffu, part, 4);
        part += __shfl_xor_sync(0xffffffffu, part, 2);
        part += __shfl_xor_sync(0xffffffffu, part, 1);
        if ((tid & 31) == 0) sm[tid >> 5] = part;
        __syncthreads();
        if (tid == 0) {
            float ssum = 0.f;
            #pragma unroll
            for (int w = 0; w < 8; w++) ssum += sm[w];
            g_bs[0] = ssum;
        }
    }
}

// ---------------------------------------------------------------------------
// MAIN: fused GBST. One CTA = 12 positions of one row. 128 threads,
// thread t owns channels {4t..4t+3} (8-byte fp16 gathers, fp32 accumulate).
// ---------------------------------------------------------------------------
__global__ __launch_bounds__(128, 5) void gbst_main_kernel(
    const int* __restrict__ ids,
    const float* __restrict__ conv_b,
    float* __restrict__ out)
{
    __shared__ int   sid[T_TILE + 4];
    __shared__ float t_s[T_TILE];
    __shared__ float wsm[T_TILE][4];

    const int row  = blockIdx.x / TPR;
    const int tile = blockIdx.x - row * TPR;
    const int r0   = tile * T_TILE;
    const int Tcur = (L_SEQ - r0 < T_TILE) ? (L_SEQ - r0) : T_TILE;  // 12 or 8
    const int tid  = threadIdx.x;

    if (tid < T_TILE + 4) {
        int j = r0 + tid - 2;
        sid[tid] = (j >= 0 && j < L_SEQ) ? ids[row * L_SEQ + j] : 0;  // id 0 -> zero row
    }
    __syncthreads();

    const float4 cb = ((const float4*)conv_b)[tid];
    const float2* __restrict__ Pb = (const float2*)g_Ph;  // slice = 128 float2 (=512 half)

    // Phase 1: conv output via fp16 table gather (8B loads, fp32 accumulate)
    float4 xs[T_TILE];
    #pragma unroll
    for (int l = 0; l < T_TILE; l++) {
        float4 x = make_float4(0.f, 0.f, 0.f, 0.f);
        if (l < Tcur) {
            x = cb;
            #pragma unroll
            for (int k = 0; k < KW; k++) {
                int v = sid[l + k];
                float2 raw = Pb[(v * KW + k) * (D_DIM / 4) + tid];
                float2 f0 = __half22float2(*(const __half2*)&raw.x);
                float2 f1 = __half22float2(*(const __half2*)&raw.y);
                x.x += f0.x; x.y += f0.y; x.z += f1.x; x.w += f1.y;
            }
        }
        xs[l] = x;
    }

    // Phase 2+3: exact scalar scores + softmax weights (warp 0 only)
    if (tid < 32) {
        if (tid < T_TILE) {
            float s = 0.f;
            if (tid < Tcur) {
                s = g_bs[0];
                #pragma unroll
                for (int k = 0; k < KW; k++) s += g_sT[sid[tid + k] * KW + k];
            }
            t_s[tid] = s;
        }
        __syncwarp();
        if (tid < T_TILE) {
            const int l = tid;
            float s1 = t_s[l];
            int j2 = l & ~1;
            float s2 = (t_s[j2] + t_s[j2 + 1]) * 0.5f;
            int j3 = l - (l % 3);
            float s3 = (t_s[j3] + t_s[j3 + 1] + t_s[j3 + 2]) * (1.f / 3.f);
            int j4 = l & ~3;
            float s4 = (t_s[j4] + t_s[j4 + 1] + t_s[j4 + 2] + t_s[j4 + 3]) * 0.25f;
            float mx = fmaxf(fmaxf(s1, s2), fmaxf(s3, s4));
            float e1 = expf(s1 - mx);
            float e2 = expf(s2 - mx);
            float e3 = expf(s3 - mx);
            float e4 = expf(s4 - mx);
            float inv = 1.f / (e1 + e2 + e3 + e4);
            wsm[l][0] = e1 * inv;
            wsm[l][1] = e2 * inv;
            wsm[l][2] = e3 * inv;
            wsm[l][3] = e4 * inv;
        }
    }
    __syncthreads();

    // Phase 4: pooled candidates, weighted combine, DS=2 pool, store
    float4 p3[T_TILE / 3];
    #pragma unroll
    for (int j = 0; j < T_TILE / 3; j++) {
        p3[j].x = (xs[3 * j].x + xs[3 * j + 1].x + xs[3 * j + 2].x) * (1.f / 3.f);
        p3[j].y = (xs[3 * j].y + xs[3 * j + 1].y + xs[3 * j + 2].y) * (1.f / 3.f);
        p3[j].z = (xs[3 * j].z + xs[3 * j + 1].z + xs[3 * j + 2].z) * (1.f / 3.f);
        p3[j].w = (xs[3 * j].w + xs[3 * j + 1].w + xs[3 * j + 2].w) * (1.f / 3.f);
    }
    float4 p4[T_TILE / 4];
    #pragma unroll
    for (int j = 0; j < T_TILE / 4; j++) {
        p4[j].x = (xs[4 * j].x + xs[4 * j + 1].x + xs[4 * j + 2].x + xs[4 * j + 3].x) * 0.25f;
        p4[j].y = (xs[4 * j].y + xs[4 * j + 1].y + xs[4 * j + 2].y + xs[4 * j + 3].y) * 0.25f;
        p4[j].z = (xs[4 * j].z + xs[4 * j + 1].z + xs[4 * j + 2].z + xs[4 * j + 3].z) * 0.25f;
        p4[j].w = (xs[4 * j].w + xs[4 * j + 1].w + xs[4 * j + 2].w + xs[4 * j + 3].w) * 0.25f;
    }

    #pragma unroll
    for (int j = 0; j < T_TILE / 2; j++) {
        const int l0 = 2 * j, l1 = 2 * j + 1;
        if (l0 < Tcur) {
            float w10 = wsm[l0][0], w11 = wsm[l1][0];
            float w2  = wsm[l0][1] + wsm[l1][1];
            float w30 = wsm[l0][2], w31 = wsm[l1][2];
            float w4  = wsm[l0][3] + wsm[l1][3];
            float4 a = xs[l0], b = xs[l1];
            float4 q3a = p3[l0 / 3], q3b = p3[l1 / 3];
            float4 q4 = p4[j >> 1];
            float4 o;
            o.x = 0.5f * (w10 * a.x + w11 * b.x + w2 * (a.x + b.x) * 0.5f + w30 * q3a.x + w31 * q3b.x + w4 * q4.x);
            o.y = 0.5f * (w10 * a.y + w11 * b.y + w2 * (a.y + b.y) * 0.5f + w30 * q3a.y + w31 * q3b.y + w4 * q4.y);
            o.z = 0.5f * (w10 * a.z + w11 * b.z + w2 * (a.z + b.z) * 0.5f + w30 * q3a.z + w31 * q3b.z + w4 * q4.z);
            o.w = 0.5f * (w10 * a.w + w11 * b.w + w2 * (a.w + b.w) * 0.5f + w30 * q3a.w + w31 * q3b.w + w4 * q4.w);
            ((float4*)out)[((size_t)row * OUTL + tile * (T_TILE / 2) + j) * (D_DIM / 4) + tid] = o;
        }
    }
}

// ---------------------------------------------------------------------------
extern "C" void kernel_launch(void* const* d_in, const int* in_sizes, int n_in,
                              void* d_out, int out_size) {
    const int*   ids     = (const int*)d_in[0];
    const float* emb     = (const float*)d_in[1];
    const float* conv_w  = (const float*)d_in[2];
    const float* conv_b  = (const float*)d_in[3];
    const float* score_w = (const float*)d_in[4];
    float* out = (float*)d_out;

    prep_kernel<<<552, 256>>>(conv_w, score_w);
    build_kernel<<<417, 256>>>(emb, conv_b, score_w);
    gbst_main_kernel<<<BATCH * TPR, 128>>>(ids, conv_b, out);
}